// round 5
// baseline (speedup 1.0000x reference)
#include <cuda_runtime.h>
#include <math_constants.h>
#include <stdint.h>

#define KTOP 6       // K+1 with K=5
#define TPB  128
#define CAP  1536    // candidate buffer capacity (expected ~68 used)
#define THR  3.0f    // candidate threshold; guarded by exact fallback
#define EGATE 20.0855369f   // exp(THR): free gate on 4-elem exp partial sums

__device__ float g_row_loss[8192];
__device__ unsigned int g_ticket = 0;

__device__ __forceinline__ void topk_insert(float (&t)[KTOP], float v) {
    float x = v;
    #pragma unroll
    for (int j = 0; j < KTOP; ++j) {
        float hi = fmaxf(t[j], x);
        float lo = fminf(t[j], x);
        t[j] = hi;
        x = lo;
    }
}

__device__ __forceinline__ void push_cand(float v, int idx, int yi,
                                          int* scnt, float* cval) {
    if (v > THR && idx != yi) {
        int pos = atomicAdd(scnt, 1);
        if (pos < CAP) cval[pos] = v;
    }
}

// Process one float4: accumulate exp-sum into s, gate candidates off the
// partial sum (free: the adds are the reduction anyway). exp monotone + >=0
// => any element > THR forces q >= exp(THR), so the gate is conservative.
__device__ __forceinline__ void proc_vec(float4 a, int base, int yi,
                                         float& s, int* scnt, float* cval) {
    float e0 = __expf(a.x), e1 = __expf(a.y), e2 = __expf(a.z), e3 = __expf(a.w);
    float q = (e0 + e1) + (e2 + e3);
    s += q;
    if (q > EGATE) {                      // ~0.5% of thread-vectors
        push_cand(a.x, base + 0, yi, scnt, cval);
        push_cand(a.y, base + 1, yi, scnt, cval);
        push_cand(a.z, base + 2, yi, scnt, cval);
        push_cand(a.w, base + 3, yi, scnt, cval);
    }
}

__global__ __launch_bounds__(TPB) void autkc_fused_kernel(
    const float* __restrict__ pred,
    const int*   __restrict__ ylab,
    int C, int B,
    float* __restrict__ out)
{
    const int row = blockIdx.x;
    const float* __restrict__ p = pred + (long long)row * (long long)C;
    const int yi  = ylab[row];
    const int tid = threadIdx.x;

    __shared__ float cval[CAP];
    __shared__ int   scnt;
    __shared__ float shsum[TPB / 32];
    __shared__ float wval[TPB / 32];
    __shared__ int   widx[TPB / 32];
    __shared__ float topv[KTOP];
    __shared__ int   is_last;

    if (tid == 0) scnt = 0;
    __syncthreads();

    float s0 = 0.f, s1 = 0.f, s2 = 0.f, s3 = 0.f;

    // ---- alignment peel (row base may not be 16B aligned; C odd) ----
    const int mis  = (int)(((uintptr_t)p & 15u) >> 2);
    const int peel = ((4 - mis) & 3);
    for (int i = tid; i < peel && i < C; i += TPB) {
        float v = p[i];
        s0 += __expf(v);
        push_cand(v, i, yi, &scnt, cval);
    }

    const int nvec = (C - peel) >> 2;
    const float4* __restrict__ pv = (const float4*)(p + peel);

    // ---- software-pipelined streaming loop: prefetch 4, compute 4 ----
    int j = tid;
    if (j + 3 * TPB < nvec) {
        float4 A0 = __ldcs(&pv[j]);
        float4 A1 = __ldcs(&pv[j +     TPB]);
        float4 A2 = __ldcs(&pv[j + 2 * TPB]);
        float4 A3 = __ldcs(&pv[j + 3 * TPB]);
        int jn = j + 4 * TPB;
        while (jn + 3 * TPB < nvec) {
            float4 B0 = __ldcs(&pv[jn]);
            float4 B1 = __ldcs(&pv[jn +     TPB]);
            float4 B2 = __ldcs(&pv[jn + 2 * TPB]);
            float4 B3 = __ldcs(&pv[jn + 3 * TPB]);
            int ba = peel + 4 * j;
            proc_vec(A0, ba,            yi, s0, &scnt, cval);
            proc_vec(A1, ba + 4 * TPB,  yi, s1, &scnt, cval);
            proc_vec(A2, ba + 8 * TPB,  yi, s2, &scnt, cval);
            proc_vec(A3, ba + 12 * TPB, yi, s3, &scnt, cval);
            A0 = B0; A1 = B1; A2 = B2; A3 = B3;
            j = jn;
            jn += 4 * TPB;
        }
        int ba = peel + 4 * j;
        proc_vec(A0, ba,            yi, s0, &scnt, cval);
        proc_vec(A1, ba + 4 * TPB,  yi, s1, &scnt, cval);
        proc_vec(A2, ba + 8 * TPB,  yi, s2, &scnt, cval);
        proc_vec(A3, ba + 12 * TPB, yi, s3, &scnt, cval);
        j = jn;
    }
    for (; j < nvec; j += TPB) {
        float4 a = __ldcs(&pv[j]);
        proc_vec(a, peel + 4 * j, yi, s0, &scnt, cval);
    }
    for (int i = peel + 4 * nvec + tid; i < C; i += TPB) {
        float v = p[i];
        s0 += __expf(v);
        push_cand(v, i, yi, &scnt, cval);
    }

    float s = (s0 + s1) + (s2 + s3);
    #pragma unroll
    for (int o = 16; o > 0; o >>= 1) s += __shfl_down_sync(0xffffffffu, s, o);
    if ((tid & 31) == 0) shsum[tid >> 5] = s;
    __syncthreads();

    // ---- candidate count check; exact fallback for adversarial input ----
    int n = scnt;
    if (n < KTOP || n > CAP) {
        float t[KTOP];
        #pragma unroll
        for (int k = 0; k < KTOP; ++k) t[k] = -CUDART_INF_F;
        float thr2 = -CUDART_INF_F;
        for (int i = tid; i < C; i += TPB) {
            float v = p[i];
            if (v > thr2 && i != yi) { topk_insert(t, v); thr2 = t[KTOP - 1]; }
        }
        __syncthreads();
        #pragma unroll
        for (int k = 0; k < KTOP; ++k) cval[tid + k * TPB] = t[k];
        n = TPB * KTOP;
        __syncthreads();
    }

    // ---- top-6 of cval[0..n): 6 masked argmax rounds ----
    for (int r = 0; r < KTOP; ++r) {
        float bv = -CUDART_INF_F;
        int   bi = 0;
        for (int i = tid; i < n; i += TPB) {
            float v = cval[i];
            if (v > bv) { bv = v; bi = i; }
        }
        #pragma unroll
        for (int o = 16; o > 0; o >>= 1) {
            float ov = __shfl_down_sync(0xffffffffu, bv, o);
            int   oi = __shfl_down_sync(0xffffffffu, bi, o);
            if (ov > bv) { bv = ov; bi = oi; }
        }
        if ((tid & 31) == 0) { wval[tid >> 5] = bv; widx[tid >> 5] = bi; }
        __syncthreads();
        if (tid == 0) {
            float best = -CUDART_INF_F;
            int   besti = 0;
            #pragma unroll
            for (int w = 0; w < TPB / 32; ++w)
                if (wval[w] > best) { best = wval[w]; besti = widx[w]; }
            topv[r] = best;
            cval[besti] = -CUDART_INF_F;
        }
        __syncthreads();
    }

    // ---- per-row loss + fused last-CTA mean ----
    if (tid == 0) {
        float S_total = 0.0f;
        #pragma unroll
        for (int w = 0; w < TPB / 32; ++w) S_total += shsum[w];
        float invS = 1.0f / S_total;
        float py   = __expf(p[yi]) * invS;
        float acc  = 0.0f;
        #pragma unroll
        for (int r = 0; r < KTOP; ++r) {
            float pi = __expf(topv[r]) * invS;
            float dd = 1.0f + pi - py;
            acc += dd * dd;
        }
        g_row_loss[row] = acc * (1.0f / (float)(KTOP - 1));   // /K
        __threadfence();
        unsigned int done = atomicAdd(&g_ticket, 1u);
        is_last = (done == (unsigned int)(B - 1)) ? 1 : 0;
    }
    __syncthreads();

    if (is_last) {
        __threadfence();
        float fs = 0.0f;
        for (int i = tid; i < B; i += TPB) fs += g_row_loss[i];
        #pragma unroll
        for (int o = 16; o > 0; o >>= 1) fs += __shfl_down_sync(0xffffffffu, fs, o);
        if ((tid & 31) == 0) shsum[tid >> 5] = fs;
        __syncthreads();
        if (tid == 0) {
            float tot = 0.0f;
            #pragma unroll
            for (int w = 0; w < TPB / 32; ++w) tot += shsum[w];
            out[0] = tot / (float)B;
            g_ticket = 0;   // reset for next graph replay
        }
    }
}

extern "C" void kernel_launch(void* const* d_in, const int* in_sizes, int n_in,
                              void* d_out, int out_size)
{
    const float* pred = (const float*)d_in[0];
    const int*   y    = (const int*)d_in[1];
    // d_in[2] = epoch, unused (AUTKC branch taken for epoch >= 0)

    const int B = in_sizes[1];
    const int C = in_sizes[0] / B;

    autkc_fused_kernel<<<B, TPB>>>(pred, y, C, B, (float*)d_out);
}

// round 6
// speedup vs baseline: 1.1131x; 1.1131x over previous
#include <cuda_runtime.h>
#include <math_constants.h>
#include <stdint.h>

#define KTOP 6       // K+1 with K=5
#define TPB  256
#define STAGES 4     // cp.async ring depth (power of 2)
#define CAP  1536    // candidate buffer capacity (expected ~68 used)
#define THR  3.0f    // candidate threshold; guarded by exact fallback
#define EGATE 20.0855369f   // exp(THR): conservative gate on 4-elem exp sums

__device__ float g_row_loss[8192];
__device__ unsigned int g_ticket = 0;

__device__ __forceinline__ uint32_t smem_u32(const void* ptr) {
    return (uint32_t)__cvta_generic_to_shared(ptr);
}
__device__ __forceinline__ void cp_async16(uint32_t dst, const void* src) {
    asm volatile("cp.async.cg.shared.global [%0], [%1], 16;" :: "r"(dst), "l"(src));
}
__device__ __forceinline__ void cp_commit() {
    asm volatile("cp.async.commit_group;");
}
__device__ __forceinline__ void cp_wait2() {
    asm volatile("cp.async.wait_group 2;");
}

__device__ __forceinline__ void topk_insert(float (&t)[KTOP], float v) {
    float x = v;
    #pragma unroll
    for (int j = 0; j < KTOP; ++j) {
        float hi = fmaxf(t[j], x);
        float lo = fminf(t[j], x);
        t[j] = hi;
        x = lo;
    }
}

__device__ __forceinline__ void push_cand(float v, int idx, int yi,
                                          int* scnt, float* cval) {
    if (v > THR && idx != yi) {
        int pos = atomicAdd(scnt, 1);
        if (pos < CAP) cval[pos] = v;
    }
}

// exp-sum one float4; gate candidate push off the partial sum (exp monotone,
// exps >= 0 => any elem > THR forces q >= exp(THR); conservative gate).
__device__ __forceinline__ void proc_vec(float4 a, int base, int yi,
                                         float& s, int* scnt, float* cval) {
    float e0 = __expf(a.x), e1 = __expf(a.y), e2 = __expf(a.z), e3 = __expf(a.w);
    float q = (e0 + e1) + (e2 + e3);
    s += q;
    if (q > EGATE) {                      // rare
        push_cand(a.x, base + 0, yi, scnt, cval);
        push_cand(a.y, base + 1, yi, scnt, cval);
        push_cand(a.z, base + 2, yi, scnt, cval);
        push_cand(a.w, base + 3, yi, scnt, cval);
    }
}

__global__ __launch_bounds__(TPB) void autkc_fused_kernel(
    const float* __restrict__ pred,
    const int*   __restrict__ ylab,
    int C, int B,
    float* __restrict__ out)
{
    const int row = blockIdx.x;
    const float* __restrict__ p = pred + (long long)row * (long long)C;
    const int yi  = ylab[row];
    const int tid = threadIdx.x;

    __shared__ alignas(16) float4 buf[STAGES][TPB];
    __shared__ float cval[CAP];
    __shared__ int   scnt;
    __shared__ float shsum[TPB / 32];
    __shared__ float wval[TPB / 32];
    __shared__ int   widx[TPB / 32];
    __shared__ float topv[KTOP];
    __shared__ int   is_last;

    if (tid == 0) scnt = 0;
    __syncthreads();

    float s0 = 0.f, s1 = 0.f;

    // ---- alignment peel (row base may not be 16B aligned; C odd) ----
    const int mis  = (int)(((uintptr_t)p & 15u) >> 2);
    const int peel = ((4 - mis) & 3);
    for (int i = tid; i < peel && i < C; i += TPB) {
        float v = p[i];
        s0 += __expf(v);
        push_cand(v, i, yi, &scnt, cval);
    }

    const int nvec = (C - peel) >> 2;
    const float4* __restrict__ pv = (const float4*)(p + peel);
    const int n_stage = nvec / TPB;       // full cp.async stages

    // ---- cp.async pipelined streaming: regs stay free, loads decoupled ----
    const uint32_t mybuf = smem_u32(&buf[0][tid]);
    #pragma unroll
    for (int s = 0; s < STAGES - 1; ++s) {
        if (s < n_stage)
            cp_async16(mybuf + (uint32_t)s * (TPB * 16u), &pv[s * TPB + tid]);
        cp_commit();
    }
    for (int st = 0; st < n_stage; ++st) {
        int pf = st + (STAGES - 1);
        if (pf < n_stage)
            cp_async16(mybuf + (uint32_t)(pf & (STAGES - 1)) * (TPB * 16u),
                       &pv[pf * TPB + tid]);
        cp_commit();
        cp_wait2();                        // stage st now resident
        float4 a = buf[st & (STAGES - 1)][tid];
        proc_vec(a, peel + 4 * (st * TPB + tid), yi,
                 (st & 1) ? s1 : s0, &scnt, cval);
    }

    // vector tail beyond full stages
    for (int jv = n_stage * TPB + tid; jv < nvec; jv += TPB) {
        float4 a = __ldcs(&pv[jv]);
        proc_vec(a, peel + 4 * jv, yi, s0, &scnt, cval);
    }
    // scalar tail
    for (int i = peel + 4 * nvec + tid; i < C; i += TPB) {
        float v = p[i];
        s0 += __expf(v);
        push_cand(v, i, yi, &scnt, cval);
    }

    float s = s0 + s1;
    #pragma unroll
    for (int o = 16; o > 0; o >>= 1) s += __shfl_down_sync(0xffffffffu, s, o);
    if ((tid & 31) == 0) shsum[tid >> 5] = s;
    __syncthreads();

    // ---- candidate count check; exact fallback for adversarial input ----
    int n = scnt;
    if (n < KTOP || n > CAP) {
        float t[KTOP];
        #pragma unroll
        for (int k = 0; k < KTOP; ++k) t[k] = -CUDART_INF_F;
        float thr2 = -CUDART_INF_F;
        for (int i = tid; i < C; i += TPB) {
            float v = p[i];
            if (v > thr2 && i != yi) { topk_insert(t, v); thr2 = t[KTOP - 1]; }
        }
        __syncthreads();
        #pragma unroll
        for (int k = 0; k < KTOP; ++k) cval[tid + k * TPB] = t[k];
        n = TPB * KTOP;
        __syncthreads();
    }

    // ---- top-6 of cval[0..n): 6 masked argmax rounds ----
    for (int r = 0; r < KTOP; ++r) {
        float bv = -CUDART_INF_F;
        int   bi = 0;
        for (int i = tid; i < n; i += TPB) {
            float v = cval[i];
            if (v > bv) { bv = v; bi = i; }
        }
        #pragma unroll
        for (int o = 16; o > 0; o >>= 1) {
            float ov = __shfl_down_sync(0xffffffffu, bv, o);
            int   oi = __shfl_down_sync(0xffffffffu, bi, o);
            if (ov > bv) { bv = ov; bi = oi; }
        }
        if ((tid & 31) == 0) { wval[tid >> 5] = bv; widx[tid >> 5] = bi; }
        __syncthreads();
        if (tid == 0) {
            float best = -CUDART_INF_F;
            int   besti = 0;
            #pragma unroll
            for (int w = 0; w < TPB / 32; ++w)
                if (wval[w] > best) { best = wval[w]; besti = widx[w]; }
            topv[r] = best;
            cval[besti] = -CUDART_INF_F;
        }
        __syncthreads();
    }

    // ---- per-row loss + fused last-CTA mean ----
    if (tid == 0) {
        float S_total = 0.0f;
        #pragma unroll
        for (int w = 0; w < TPB / 32; ++w) S_total += shsum[w];
        float invS = 1.0f / S_total;
        float py   = __expf(p[yi]) * invS;
        float acc  = 0.0f;
        #pragma unroll
        for (int r = 0; r < KTOP; ++r) {
            float pi = __expf(topv[r]) * invS;
            float dd = 1.0f + pi - py;
            acc += dd * dd;
        }
        g_row_loss[row] = acc * (1.0f / (float)(KTOP - 1));   // /K
        __threadfence();
        unsigned int done = atomicAdd(&g_ticket, 1u);
        is_last = (done == (unsigned int)(B - 1)) ? 1 : 0;
    }
    __syncthreads();

    if (is_last) {
        __threadfence();
        float fs = 0.0f;
        for (int i = tid; i < B; i += TPB) fs += g_row_loss[i];
        #pragma unroll
        for (int o = 16; o > 0; o >>= 1) fs += __shfl_down_sync(0xffffffffu, fs, o);
        if ((tid & 31) == 0) shsum[tid >> 5] = fs;
        __syncthreads();
        if (tid == 0) {
            float tot = 0.0f;
            #pragma unroll
            for (int w = 0; w < TPB / 32; ++w) tot += shsum[w];
            out[0] = tot / (float)B;
            g_ticket = 0;   // reset for next graph replay
        }
    }
}

extern "C" void kernel_launch(void* const* d_in, const int* in_sizes, int n_in,
                              void* d_out, int out_size)
{
    const float* pred = (const float*)d_in[0];
    const int*   y    = (const int*)d_in[1];
    // d_in[2] = epoch, unused (AUTKC branch taken for epoch >= 0)

    const int B = in_sizes[1];
    const int C = in_sizes[0] / B;

    autkc_fused_kernel<<<B, TPB>>>(pred, y, C, B, (float*)d_out);
}